// round 3
// baseline (speedup 1.0000x reference)
#include <cuda_runtime.h>
#include <cstdint>

// ---------------------------------------------------------------------------
// Problem constants
// ---------------------------------------------------------------------------
#define NROWS 32768            // 64*512
#define KC    1024             // num centers
#define DDIM  256              // latent dim
#define BM    128              // CTA tile M
#define BN    128              // CTA tile N
#define BKC   32               // K-chunk (floats)
#define NCHUNK (DDIM / BKC)    // 8
#define CBLK  (KC / BN)        // 8 column blocks

#define A_STAGE 16384          // 128 rows * 32 floats * 4B
#define B_STAGE 16384
#define SMEM_SZ (2 * A_STAGE + 2 * B_STAGE)   // 65536

// ---------------------------------------------------------------------------
// Device-global scratch (no allocations allowed)
// ---------------------------------------------------------------------------
__device__ uint32_t g_ztf[(size_t)NROWS * DDIM];   // tf32-rounded z   (32 MB)
__device__ uint32_t g_ctf[(size_t)KC * DDIM];      // tf32-rounded c   (1 MB)
__device__ float    g_zsq[NROWS];
__device__ float    g_csq[KC];
__device__ float    g_part[CBLK * NROWS];          // per-colblock row sums

// ---------------------------------------------------------------------------
// helpers (sm_80-era PTX only: works on plain sm_100 target)
// ---------------------------------------------------------------------------
__device__ __forceinline__ uint32_t smem_u32(const void* p) {
    uint32_t a;
    asm("{ .reg .u64 t; cvta.to.shared.u64 t, %1; cvt.u32.u64 %0, t; }"
        : "=r"(a) : "l"(p));
    return a;
}

__device__ __forceinline__ void cpasync16(uint32_t dst, const void* src) {
    asm volatile("cp.async.cg.shared.global [%0], [%1], 16;"
                 :: "r"(dst), "l"(src));
}

__device__ __forceinline__ void ldsm4(uint32_t addr, uint32_t* d) {
    asm volatile("ldmatrix.sync.aligned.m8n8.x4.shared.b16 {%0,%1,%2,%3}, [%4];"
                 : "=r"(d[0]), "=r"(d[1]), "=r"(d[2]), "=r"(d[3])
                 : "r"(addr));
}

__device__ __forceinline__ void mma_tf32(float* c, const uint32_t* a,
                                         uint32_t b0, uint32_t b1) {
    asm volatile(
        "mma.sync.aligned.m16n8k8.row.col.f32.tf32.tf32.f32 "
        "{%0,%1,%2,%3}, {%4,%5,%6,%7}, {%8,%9}, {%0,%1,%2,%3};"
        : "+f"(c[0]), "+f"(c[1]), "+f"(c[2]), "+f"(c[3])
        : "r"(a[0]), "r"(a[1]), "r"(a[2]), "r"(a[3]), "r"(b0), "r"(b1));
}

__device__ __forceinline__ uint32_t f2tf32(float x) {
    uint32_t u;
    asm("cvt.rna.tf32.f32 %0, %1;" : "=r"(u) : "f"(x));
    return u;
}

// ---------------------------------------------------------------------------
// Kernel 1: prep — squared norms + tf32-rounded copies
// one warp per row (of z or centers)
// ---------------------------------------------------------------------------
__global__ void prep_kernel(const float* __restrict__ z,
                            const float* __restrict__ c) {
    int gw   = (blockIdx.x * blockDim.x + threadIdx.x) >> 5;
    int lane = threadIdx.x & 31;
    if (gw >= NROWS + KC) return;

    const float* src;
    uint32_t*    dst;
    if (gw < NROWS) { src = z + (size_t)gw * DDIM;            dst = g_ztf + (size_t)gw * DDIM; }
    else            { src = c + (size_t)(gw - NROWS) * DDIM;  dst = g_ctf + (size_t)(gw - NROWS) * DDIM; }

    const float4* s4 = (const float4*)src;
    uint4*        d4 = (uint4*)dst;
    float s = 0.0f;
    #pragma unroll
    for (int i = 0; i < 2; i++) {
        float4 v = s4[lane + 32 * i];
        s += v.x * v.x + v.y * v.y + v.z * v.z + v.w * v.w;
        uint4 o;
        o.x = f2tf32(v.x); o.y = f2tf32(v.y);
        o.z = f2tf32(v.z); o.w = f2tf32(v.w);
        d4[lane + 32 * i] = o;
    }
    #pragma unroll
    for (int o = 16; o > 0; o >>= 1) s += __shfl_down_sync(0xffffffffu, s, o);
    if (lane == 0) {
        if (gw < NROWS) g_zsq[gw] = s;
        else            g_csq[gw - NROWS] = s;
    }
}

// ---------------------------------------------------------------------------
// Kernel 2: TF32 mma.sync GEMM + fused Student-t epilogue + rowsum partials
// grid (CBLK=8, NROWS/BM=256), 256 threads (8 warps: 4 along M x 2 along N)
// ---------------------------------------------------------------------------
__global__ void __launch_bounds__(256)
gemm_kernel(float* __restrict__ out) {
    extern __shared__ char smem[];
    uint32_t sb = smem_u32(smem);
    const uint32_t A0 = sb;                 // A stages at sb + s*A_STAGE
    const uint32_t B0 = sb + 2 * A_STAGE;   // B stages at B0 + s*B_STAGE

    int tid  = threadIdx.x;
    int wid  = tid >> 5;
    int lane = tid & 31;
    int cb   = blockIdx.x;
    int rb   = blockIdx.y;
    int gr0  = rb * BM;
    int gc0  = cb * BN;
    int wm0  = (wid & 3) * 32;     // warp M offset within CTA tile
    int wn0  = (wid >> 2) * 64;    // warp N offset

    // ---------------- cp.async tile loader (16B XOR swizzle) ----------------
    auto load_chunk = [&](int i, int s) {
        const uint32_t* gA = g_ztf + (size_t)gr0 * DDIM + i * BKC;
        const uint32_t* gB = g_ctf + (size_t)gc0 * DDIM + i * BKC;
        uint32_t ab = A0 + s * A_STAGE;
        uint32_t bb = B0 + s * B_STAGE;
        #pragma unroll
        for (int u = 0; u < 4; u++) {            // 1024 float4 / 256 threads
            int f   = u * 256 + tid;
            int row = f >> 3, c4 = f & 7;
            cpasync16(ab + row * 128 + 16 * (c4 ^ (row & 7)),
                      gA + (size_t)row * DDIM + c4 * 4);
        }
        #pragma unroll
        for (int u = 0; u < 4; u++) {
            int f   = u * 256 + tid;
            int row = f >> 3, c4 = f & 7;
            cpasync16(bb + row * 128 + 16 * (c4 ^ (row & 7)),
                      gB + (size_t)row * DDIM + c4 * 4);
        }
        asm volatile("cp.async.commit_group;");
    };

    // ---------------- ldmatrix address precompute ----------------
    // x4 convention: thread t supplies row address of matrix (t>>3), row (t&7)
    int g = lane >> 3, r = lane & 7;
    // A: matrices {rows+0..7,u0},{rows+8..15,u0},{rows+0..7,u1},{rows+8..15,u1}
    uint32_t aRow[2], aSw[2];
    #pragma unroll
    for (int ms = 0; ms < 2; ms++) {
        int row = wm0 + ms * 16 + (g & 1) * 8 + r;
        aRow[ms] = (uint32_t)row * 128;
        aSw[ms]  = (uint32_t)(row & 7);
    }
    uint32_t aDu = (uint32_t)(g >> 1);
    // B: matrices {n+0..7,u0},{n+0..7,u1},{n+8..15,u0},{n+8..15,u1}
    uint32_t bRow[4], bSw[4];
    #pragma unroll
    for (int nj = 0; nj < 4; nj++) {
        int row = wn0 + nj * 16 + (g >> 1) * 8 + r;
        bRow[nj] = (uint32_t)row * 128;
        bSw[nj]  = (uint32_t)(row & 7);
    }
    uint32_t bDu = (uint32_t)(g & 1);

    float acc[2][8][4];
    #pragma unroll
    for (int ms = 0; ms < 2; ms++)
        #pragma unroll
        for (int ns = 0; ns < 8; ns++)
            #pragma unroll
            for (int q = 0; q < 4; q++) acc[ms][ns][q] = 0.0f;

    // ---------------- mainloop ----------------
    load_chunk(0, 0);
    load_chunk(1, 1);

    for (int i = 0; i < NCHUNK; i++) {
        int s = i & 1;
        if (i < NCHUNK - 1) asm volatile("cp.async.wait_group 1;");
        else                asm volatile("cp.async.wait_group 0;");
        __syncthreads();

        uint32_t ab = A0 + s * A_STAGE;
        uint32_t bb = B0 + s * B_STAGE;
        #pragma unroll
        for (int kk = 0; kk < 4; kk++) {
            uint32_t afr[2][4], bfr[4][4];
            #pragma unroll
            for (int ms = 0; ms < 2; ms++)
                ldsm4(ab + aRow[ms] + 16 * ((2 * kk + aDu) ^ aSw[ms]), afr[ms]);
            #pragma unroll
            for (int nj = 0; nj < 4; nj++)
                ldsm4(bb + bRow[nj] + 16 * ((2 * kk + bDu) ^ bSw[nj]), bfr[nj]);
            #pragma unroll
            for (int ms = 0; ms < 2; ms++)
                #pragma unroll
                for (int ns = 0; ns < 8; ns++)
                    mma_tf32(acc[ms][ns], afr[ms],
                             bfr[ns >> 1][(ns & 1) * 2],
                             bfr[ns >> 1][(ns & 1) * 2 + 1]);
        }
        __syncthreads();
        if (i + 2 < NCHUNK) load_chunk(i + 2, s);
    }

    // ---------------- epilogue: Student-t + rowsum partials ----------------
    int tig = lane & 3, gid = lane >> 2;
    float rs[2][2] = {{0.f, 0.f}, {0.f, 0.f}};   // [ms][row-half]

    #pragma unroll
    for (int ms = 0; ms < 2; ms++) {
        int r0 = gr0 + wm0 + 16 * ms + gid;      // rows r0 and r0+8
        float zs0 = g_zsq[r0];
        float zs1 = g_zsq[r0 + 8];
        #pragma unroll
        for (int ns = 0; ns < 8; ns++) {
            int col = gc0 + wn0 + 8 * ns + 2 * tig;
            float cs0 = g_csq[col], cs1 = g_csq[col + 1];

            float d00 = fmaxf(fmaf(-2.0f, acc[ms][ns][0], zs0 + cs0), 0.0f);
            float d01 = fmaxf(fmaf(-2.0f, acc[ms][ns][1], zs0 + cs1), 0.0f);
            float d10 = fmaxf(fmaf(-2.0f, acc[ms][ns][2], zs1 + cs0), 0.0f);
            float d11 = fmaxf(fmaf(-2.0f, acc[ms][ns][3], zs1 + cs1), 0.0f);

            float s00, s01, s10, s11;
            {
                float x = fmaf(d00, 0.1f, 1.0f); float y = rsqrtf(x);
                float y2 = y * y, y4 = y2 * y2, y8 = y4 * y4; s00 = y8 * y2 * y;
            }
            {
                float x = fmaf(d01, 0.1f, 1.0f); float y = rsqrtf(x);
                float y2 = y * y, y4 = y2 * y2, y8 = y4 * y4; s01 = y8 * y2 * y;
            }
            {
                float x = fmaf(d10, 0.1f, 1.0f); float y = rsqrtf(x);
                float y2 = y * y, y4 = y2 * y2, y8 = y4 * y4; s10 = y8 * y2 * y;
            }
            {
                float x = fmaf(d11, 0.1f, 1.0f); float y = rsqrtf(x);
                float y2 = y * y, y4 = y2 * y2, y8 = y4 * y4; s11 = y8 * y2 * y;
            }
            rs[ms][0] += s00 + s01;
            rs[ms][1] += s10 + s11;

            float2* p0 = (float2*)(out + (size_t)r0 * KC + col);
            float2* p1 = (float2*)(out + (size_t)(r0 + 8) * KC + col);
            *p0 = make_float2(s00, s01);
            *p1 = make_float2(s10, s11);
        }
    }

    // reduce rowsums across the 4 lanes of each quad (same row)
    #pragma unroll
    for (int ms = 0; ms < 2; ms++)
        #pragma unroll
        for (int h = 0; h < 2; h++) {
            float v = rs[ms][h];
            v += __shfl_xor_sync(0xffffffffu, v, 1);
            v += __shfl_xor_sync(0xffffffffu, v, 2);
            rs[ms][h] = v;
        }

    __syncthreads();                 // smem tiles no longer needed
    float* red = (float*)smem;       // [128 rows][2 warp_n]
    if (tig == 0) {
        #pragma unroll
        for (int ms = 0; ms < 2; ms++)
            #pragma unroll
            for (int h = 0; h < 2; h++)
                red[(wm0 + 16 * ms + 8 * h + gid) * 2 + (wid >> 2)] = rs[ms][h];
    }
    __syncthreads();
    if (tid < BM)
        g_part[cb * NROWS + gr0 + tid] = red[tid * 2] + red[tid * 2 + 1];
}

// ---------------------------------------------------------------------------
// Kernel 3: row-normalize
// ---------------------------------------------------------------------------
__global__ void norm_kernel(float* __restrict__ out) {
    uint32_t idx = blockIdx.x * blockDim.x + threadIdx.x;  // float4 index
    uint32_t row = idx >> 8;                               // 256 float4 / row
    float s = 0.0f;
    #pragma unroll
    for (int p = 0; p < CBLK; p++) s += g_part[p * NROWS + row];
    float inv = 1.0f / s;
    float4* p4 = (float4*)out + idx;
    float4 v = *p4;
    v.x *= inv; v.y *= inv; v.z *= inv; v.w *= inv;
    *p4 = v;
}

// ---------------------------------------------------------------------------
extern "C" void kernel_launch(void* const* d_in, const int* in_sizes, int n_in,
                              void* d_out, int out_size) {
    const float* z = (const float*)d_in[0];
    const float* c = (const float*)d_in[1];
    if (in_sizes[0] == KC * DDIM) {          // defensive: metadata order
        const float* t = z; z = c; c = t;
    }
    float* out = (float*)d_out;

    static int smem_set = 0;
    if (!smem_set) {
        cudaFuncSetAttribute(gemm_kernel,
                             cudaFuncAttributeMaxDynamicSharedMemorySize, SMEM_SZ);
        smem_set = 1;
    }

    prep_kernel<<<4224, 256>>>(z, c);                       // 33792 warps
    gemm_kernel<<<dim3(CBLK, NROWS / BM), 256, SMEM_SZ>>>(out);
    norm_kernel<<<NROWS * KC / 4 / 256, 256>>>(out);
}

// round 4
// speedup vs baseline: 1.0206x; 1.0206x over previous
#include <cuda_runtime.h>
#include <cstdint>

// ---------------------------------------------------------------------------
// Problem constants
// ---------------------------------------------------------------------------
#define NROWS 32768            // 64*512
#define KC    1024             // num centers
#define DDIM  256              // latent dim
#define BM    128              // CTA rows; each CTA owns ALL 1024 output cols
#define BN    256              // column block per GEMM pass
#define NCB   (KC / BN)        // 4 column blocks
#define NJ    (NCB * 8)        // 32 flat B-chunk iterations (8 K-chunks each)

#define A_BYTES (BM * DDIM * 4)        // 131072 (A tile resident)
#define B_STAGE (BN * 32 * 4)          // 32768 per stage
#define SMEM_SZ (A_BYTES + 2 * B_STAGE)  // 196608

// ---------------------------------------------------------------------------
// Device-global scratch
// ---------------------------------------------------------------------------
__device__ float g_zsq[NROWS];
__device__ float g_csq[KC];

// ---------------------------------------------------------------------------
// helpers (sm_80-era PTX only — plain sm_100 target)
// ---------------------------------------------------------------------------
__device__ __forceinline__ uint32_t smem_u32(const void* p) {
    uint32_t a;
    asm("{ .reg .u64 t; cvta.to.shared.u64 t, %1; cvt.u32.u64 %0, t; }"
        : "=r"(a) : "l"(p));
    return a;
}
__device__ __forceinline__ void cpasync16(uint32_t dst, const void* src) {
    asm volatile("cp.async.cg.shared.global [%0], [%1], 16;"
                 :: "r"(dst), "l"(src));
}
__device__ __forceinline__ void ldsm4(uint32_t addr, uint32_t* d) {
    asm volatile("ldmatrix.sync.aligned.m8n8.x4.shared.b16 {%0,%1,%2,%3}, [%4];"
                 : "=r"(d[0]), "=r"(d[1]), "=r"(d[2]), "=r"(d[3])
                 : "r"(addr));
}
__device__ __forceinline__ void mma_tf32(float* c, const uint32_t* a,
                                         uint32_t b0, uint32_t b1) {
    asm volatile(
        "mma.sync.aligned.m16n8k8.row.col.f32.tf32.tf32.f32 "
        "{%0,%1,%2,%3}, {%4,%5,%6,%7}, {%8,%9}, {%0,%1,%2,%3};"
        : "+f"(c[0]), "+f"(c[1]), "+f"(c[2]), "+f"(c[3])
        : "r"(a[0]), "r"(a[1]), "r"(a[2]), "r"(a[3]), "r"(b0), "r"(b1));
}

// ---------------------------------------------------------------------------
// Kernel 1: prep — squared row norms only (raw f32 is fed to tf32 MMA)
// ---------------------------------------------------------------------------
__global__ void prep_kernel(const float* __restrict__ z,
                            const float* __restrict__ c) {
    int gw   = (blockIdx.x * blockDim.x + threadIdx.x) >> 5;
    int lane = threadIdx.x & 31;
    if (gw >= NROWS + KC) return;
    const float4* s4 = (gw < NROWS)
        ? (const float4*)(z + (size_t)gw * DDIM)
        : (const float4*)(c + (size_t)(gw - NROWS) * DDIM);
    float4 a = s4[lane], b = s4[lane + 32];
    float s = a.x * a.x + a.y * a.y + a.z * a.z + a.w * a.w
            + b.x * b.x + b.y * b.y + b.z * b.z + b.w * b.w;
    #pragma unroll
    for (int o = 16; o > 0; o >>= 1) s += __shfl_down_sync(0xffffffffu, s, o);
    if (lane == 0) {
        if (gw < NROWS) g_zsq[gw] = s;
        else            g_csq[gw - NROWS] = s;
    }
}

// ---------------------------------------------------------------------------
// Kernel 2: full-row fused GEMM + Student-t + in-CTA normalization
// grid = 256 CTAs (one per 128-row block), 256 threads (8 warps, tile 64x64)
// ---------------------------------------------------------------------------
__global__ void __launch_bounds__(256)
gemm_kernel(const float* __restrict__ z, const float* __restrict__ cen,
            float* __restrict__ out) {
    extern __shared__ __align__(16) char smem[];
    uint32_t sb = smem_u32(smem);
    const uint32_t A0 = sb;
    const uint32_t B0 = sb + A_BYTES;

    int tid  = threadIdx.x;
    int wid  = tid >> 5;
    int lane = tid & 31;
    int gr0  = blockIdx.x * BM;
    int wm   = (wid & 1) * 64;          // warp M offset
    int wn   = (wid >> 1) * 64;         // warp N offset (within BN)
    int wnid = wid >> 1;

    // ---- load resident A tile (128 x 256 f32 = 8192 float4) ----
    #pragma unroll
    for (int u = 0; u < 32; u++) {
        int f = u * 256 + tid;
        int row = f >> 6, c16 = f & 63;          // c16: float4 idx in row
        cpasync16(A0 + (c16 >> 3) * 16384 + row * 128 + 16 * ((c16 & 7) ^ (row & 7)),
                  z + (size_t)(gr0 + row) * DDIM + c16 * 4);
    }
    asm volatile("cp.async.commit_group;");

    // ---- B chunk loader: j -> (cb = j>>3, k = j&7), stage j&1 ----
    auto load_B = [&](int j) {
        int cb = j >> 3, k = j & 7;
        uint32_t bb = B0 + (j & 1) * B_STAGE;
        const float* gB = cen + (size_t)(cb * BN) * DDIM + k * 32;
        #pragma unroll
        for (int u = 0; u < 8; u++) {            // 2048 float4 / 256 threads
            int f = u * 256 + tid;
            int row = f >> 3, c4 = f & 7;
            cpasync16(bb + row * 128 + 16 * (c4 ^ (row & 7)),
                      gB + (size_t)row * DDIM + c4 * 4);
        }
        asm volatile("cp.async.commit_group;");
    };
    load_B(0);
    load_B(1);

    // ---- ldmatrix address precompute ----
    int g = lane >> 3, r = lane & 7;
    uint32_t aOff[4], aSw[4];
    #pragma unroll
    for (int ms = 0; ms < 4; ms++) {
        int row = wm + ms * 16 + (g & 1) * 8 + r;
        aOff[ms] = (uint32_t)row * 128;
        aSw[ms]  = (uint32_t)(row & 7);
    }
    uint32_t aDu = (uint32_t)(g >> 1);
    uint32_t bOff[4], bSw[4];
    #pragma unroll
    for (int nj = 0; nj < 4; nj++) {
        int row = wn + nj * 16 + (g >> 1) * 8 + r;
        bOff[nj] = (uint32_t)row * 128;
        bSw[nj]  = (uint32_t)(row & 7);
    }
    uint32_t bDu = (uint32_t)(g & 1);

    float acc[4][8][4];
    #pragma unroll
    for (int ms = 0; ms < 4; ms++)
        #pragma unroll
        for (int ns = 0; ns < 8; ns++)
            #pragma unroll
            for (int q = 0; q < 4; q++) acc[ms][ns][q] = 0.0f;

    int tig = lane & 3, gid = lane >> 2;
    float rs[4][2];
    #pragma unroll
    for (int ms = 0; ms < 4; ms++) { rs[ms][0] = 0.f; rs[ms][1] = 0.f; }

    // ---- flat mainloop over 32 B-chunks (4 col blocks x 8 K-chunks) ----
    #pragma unroll 1
    for (int j = 0; j < NJ; j++) {
        if (j < NJ - 1) asm volatile("cp.async.wait_group 1;");
        else            asm volatile("cp.async.wait_group 0;");
        __syncthreads();

        uint32_t ab = A0 + (j & 7) * 16384;
        uint32_t bb = B0 + (j & 1) * B_STAGE;
        #pragma unroll
        for (int kk = 0; kk < 4; kk++) {
            uint32_t afr[4][4], bfr[4][4];
            #pragma unroll
            for (int ms = 0; ms < 4; ms++)
                ldsm4(ab + aOff[ms] + 16 * ((2 * kk + aDu) ^ aSw[ms]), afr[ms]);
            #pragma unroll
            for (int nj = 0; nj < 4; nj++)
                ldsm4(bb + bOff[nj] + 16 * ((2 * kk + bDu) ^ bSw[nj]), bfr[nj]);
            #pragma unroll
            for (int ms = 0; ms < 4; ms++)
                #pragma unroll
                for (int ns = 0; ns < 8; ns++)
                    mma_tf32(acc[ms][ns], afr[ms],
                             bfr[ns >> 1][(ns & 1) * 2],
                             bfr[ns >> 1][(ns & 1) * 2 + 1]);
        }
        __syncthreads();
        if (j + 2 < NJ) load_B(j + 2);

        if ((j & 7) == 7) {
            // ---- epilogue for finished column block (overlaps B prefetch) ----
            int cb = j >> 3;
            #pragma unroll
            for (int ms = 0; ms < 4; ms++) {
                int r0 = gr0 + wm + 16 * ms + gid;
                float zs0 = g_zsq[r0];
                float zs1 = g_zsq[r0 + 8];
                #pragma unroll
                for (int ns = 0; ns < 8; ns++) {
                    int col = cb * BN + wn + 8 * ns + 2 * tig;
                    float cs0 = __ldg(&g_csq[col]);
                    float cs1 = __ldg(&g_csq[col + 1]);
                    float d00 = fmaxf(fmaf(-2.0f, acc[ms][ns][0], zs0 + cs0), 0.0f);
                    float d01 = fmaxf(fmaf(-2.0f, acc[ms][ns][1], zs0 + cs1), 0.0f);
                    float d10 = fmaxf(fmaf(-2.0f, acc[ms][ns][2], zs1 + cs0), 0.0f);
                    float d11 = fmaxf(fmaf(-2.0f, acc[ms][ns][3], zs1 + cs1), 0.0f);
                    float s00, s01, s10, s11;
                    { float x = fmaf(d00, 0.1f, 1.0f); float y = rsqrtf(x);
                      float y2 = y*y, y4 = y2*y2, y8 = y4*y4; s00 = y8*y2*y; }
                    { float x = fmaf(d01, 0.1f, 1.0f); float y = rsqrtf(x);
                      float y2 = y*y, y4 = y2*y2, y8 = y4*y4; s01 = y8*y2*y; }
                    { float x = fmaf(d10, 0.1f, 1.0f); float y = rsqrtf(x);
                      float y2 = y*y, y4 = y2*y2, y8 = y4*y4; s10 = y8*y2*y; }
                    { float x = fmaf(d11, 0.1f, 1.0f); float y = rsqrtf(x);
                      float y2 = y*y, y4 = y2*y2, y8 = y4*y4; s11 = y8*y2*y; }
                    rs[ms][0] += s00 + s01;
                    rs[ms][1] += s10 + s11;
                    *(float2*)(out + (size_t)r0 * KC + col)       = make_float2(s00, s01);
                    *(float2*)(out + (size_t)(r0 + 8) * KC + col) = make_float2(s10, s11);
                    // zero acc for next column block
                    acc[ms][ns][0] = 0.f; acc[ms][ns][1] = 0.f;
                    acc[ms][ns][2] = 0.f; acc[ms][ns][3] = 0.f;
                }
            }
        }
    }

    // ---- row-sum reduction: quad -> smem -> inv per row ----
    #pragma unroll
    for (int ms = 0; ms < 4; ms++)
        #pragma unroll
        for (int h = 0; h < 2; h++) {
            float v = rs[ms][h];
            v += __shfl_xor_sync(0xffffffffu, v, 1);
            v += __shfl_xor_sync(0xffffffffu, v, 2);
            rs[ms][h] = v;
        }
    float* red = (float*)(smem + A_BYTES);   // B stages are dead now
    float* inv = red + 512;
    if (tig == 0) {
        #pragma unroll
        for (int ms = 0; ms < 4; ms++)
            #pragma unroll
            for (int h = 0; h < 2; h++)
                red[(wm + 16 * ms + 8 * h + gid) * 4 + wnid] = rs[ms][h];
    }
    __syncthreads();
    if (tid < BM) {
        float s = red[tid * 4] + red[tid * 4 + 1] + red[tid * 4 + 2] + red[tid * 4 + 3];
        inv[tid] = 1.0f / s;
    }
    __syncthreads();

    // ---- in-CTA normalization pass over own 512KB tile (L2-hot) ----
    float4* o4 = (float4*)out + (size_t)gr0 * (KC / 4);
    #pragma unroll 4
    for (int u = 0; u < 128; u++) {          // iteration u == row u of the tile
        float iv = inv[u];
        float4 v = o4[u * 256 + tid];
        v.x *= iv; v.y *= iv; v.z *= iv; v.w *= iv;
        o4[u * 256 + tid] = v;
    }
}

// ---------------------------------------------------------------------------
extern "C" void kernel_launch(void* const* d_in, const int* in_sizes, int n_in,
                              void* d_out, int out_size) {
    const float* z = (const float*)d_in[0];
    const float* c = (const float*)d_in[1];
    if (in_sizes[0] == KC * DDIM) {          // defensive: metadata order
        const float* t = z; z = c; c = t;
    }
    float* out = (float*)d_out;

    static int smem_set = 0;
    if (!smem_set) {
        cudaFuncSetAttribute(gemm_kernel,
                             cudaFuncAttributeMaxDynamicSharedMemorySize, SMEM_SZ);
        smem_set = 1;
    }

    prep_kernel<<<4224, 256>>>(z, c);
    gemm_kernel<<<NROWS / BM, 256, SMEM_SZ>>>(z, c, out);
}

// round 5
// speedup vs baseline: 1.0474x; 1.0263x over previous
#include <cuda_runtime.h>
#include <cstdint>

// ---------------------------------------------------------------------------
// Problem constants
// ---------------------------------------------------------------------------
#define NROWS 32768            // 64*512
#define KC    1024             // num centers
#define DDIM  256              // latent dim
#define BM    128              // CTA rows; CTA owns ALL 1024 output cols
#define BN    128              // column block per GEMM pass
#define NCB   (KC / BN)        // 8 column blocks
#define NJ    (NCB * 8)        // 64 flat (cb,k) iterations

#define A_STAGE 16384          // 128 x 32 f32
#define B_STAGE 16384
#define SMEM_SZ (2 * A_STAGE + 2 * B_STAGE)   // 65536 -> 2 CTAs/SM

// ---------------------------------------------------------------------------
// Device-global scratch
// ---------------------------------------------------------------------------
__device__ float g_zsq[NROWS];
__device__ float g_csq[KC];

// ---------------------------------------------------------------------------
// helpers (sm_80-era PTX only — plain sm_100 target)
// ---------------------------------------------------------------------------
__device__ __forceinline__ uint32_t smem_u32(const void* p) {
    uint32_t a;
    asm("{ .reg .u64 t; cvta.to.shared.u64 t, %1; cvt.u32.u64 %0, t; }"
        : "=r"(a) : "l"(p));
    return a;
}
__device__ __forceinline__ void cpasync16(uint32_t dst, const void* src) {
    asm volatile("cp.async.cg.shared.global [%0], [%1], 16;"
                 :: "r"(dst), "l"(src));
}
__device__ __forceinline__ void ldsm4(uint32_t addr, uint32_t* d) {
    asm volatile("ldmatrix.sync.aligned.m8n8.x4.shared.b16 {%0,%1,%2,%3}, [%4];"
                 : "=r"(d[0]), "=r"(d[1]), "=r"(d[2]), "=r"(d[3])
                 : "r"(addr));
}
__device__ __forceinline__ void mma_tf32(float* c, const uint32_t* a,
                                         uint32_t b0, uint32_t b1) {
    asm volatile(
        "mma.sync.aligned.m16n8k8.row.col.f32.tf32.tf32.f32 "
        "{%0,%1,%2,%3}, {%4,%5,%6,%7}, {%8,%9}, {%0,%1,%2,%3};"
        : "+f"(c[0]), "+f"(c[1]), "+f"(c[2]), "+f"(c[3])
        : "r"(a[0]), "r"(a[1]), "r"(a[2]), "r"(a[3]), "r"(b0), "r"(b1));
}

// ---------------------------------------------------------------------------
// Kernel 1: prep — squared row norms
// ---------------------------------------------------------------------------
__global__ void prep_kernel(const float* __restrict__ z,
                            const float* __restrict__ c) {
    int gw   = (blockIdx.x * blockDim.x + threadIdx.x) >> 5;
    int lane = threadIdx.x & 31;
    if (gw >= NROWS + KC) return;
    const float4* s4 = (gw < NROWS)
        ? (const float4*)(z + (size_t)gw * DDIM)
        : (const float4*)(c + (size_t)(gw - NROWS) * DDIM);
    float4 a = s4[lane], b = s4[lane + 32];
    float s = a.x * a.x + a.y * a.y + a.z * a.z + a.w * a.w
            + b.x * b.x + b.y * b.y + b.z * b.z + b.w * b.w;
    #pragma unroll
    for (int o = 16; o > 0; o >>= 1) s += __shfl_down_sync(0xffffffffu, s, o);
    if (lane == 0) {
        if (gw < NROWS) g_zsq[gw] = s;
        else            g_csq[gw - NROWS] = s;
    }
}

// ---------------------------------------------------------------------------
// Kernel 2: full-row fused GEMM + Student-t + in-CTA normalization
// grid = 256 CTAs (ALL resident: 2/SM), 256 threads, warp tile 32x64
// ---------------------------------------------------------------------------
__global__ void __launch_bounds__(256, 2)
gemm_kernel(const float* __restrict__ z, const float* __restrict__ cen,
            float* __restrict__ out) {
    extern __shared__ __align__(16) char smem[];
    uint32_t sb = smem_u32(smem);
    const uint32_t A0 = sb;
    const uint32_t B0 = sb + 2 * A_STAGE;

    int tid  = threadIdx.x;
    int wid  = tid >> 5;
    int lane = tid & 31;
    int gr0  = blockIdx.x * BM;
    int wm   = (wid & 3) * 32;          // warp M offset (4 warps along M)
    int wn   = (wid >> 2) * 64;         // warp N offset (2 warps along N)
    int wnid = wid >> 2;

    // ---- chunk loader: j -> (cb = j>>3, k = j&7), stage j&1 ----
    auto load_chunk = [&](int j) {
        int cb = j >> 3, k = j & 7;
        uint32_t ab = A0 + (j & 1) * A_STAGE;
        uint32_t bb = B0 + (j & 1) * B_STAGE;
        const float* gA = z   + (size_t)gr0 * DDIM + k * 32;
        const float* gB = cen + (size_t)(cb * BN) * DDIM + k * 32;
        #pragma unroll
        for (int u = 0; u < 4; u++) {            // 1024 float4 / 256 threads
            int f = u * 256 + tid;
            int row = f >> 3, c4 = f & 7;
            cpasync16(ab + row * 128 + 16 * (c4 ^ (row & 7)),
                      gA + (size_t)row * DDIM + c4 * 4);
        }
        #pragma unroll
        for (int u = 0; u < 4; u++) {
            int f = u * 256 + tid;
            int row = f >> 3, c4 = f & 7;
            cpasync16(bb + row * 128 + 16 * (c4 ^ (row & 7)),
                      gB + (size_t)row * DDIM + c4 * 4);
        }
        asm volatile("cp.async.commit_group;");
    };
    load_chunk(0);
    load_chunk(1);

    // ---- ldmatrix address precompute ----
    int g = lane >> 3, r = lane & 7;
    uint32_t aOff[2], aSw[2];
    #pragma unroll
    for (int ms = 0; ms < 2; ms++) {
        int row = wm + ms * 16 + (g & 1) * 8 + r;
        aOff[ms] = (uint32_t)row * 128;
        aSw[ms]  = (uint32_t)(row & 7);
    }
    uint32_t aDu = (uint32_t)(g >> 1);
    uint32_t bOff[4], bSw[4];
    #pragma unroll
    for (int nj = 0; nj < 4; nj++) {
        int row = wn + nj * 16 + (g >> 1) * 8 + r;
        bOff[nj] = (uint32_t)row * 128;
        bSw[nj]  = (uint32_t)(row & 7);
    }
    uint32_t bDu = (uint32_t)(g & 1);

    float acc[2][8][4];
    #pragma unroll
    for (int ms = 0; ms < 2; ms++)
        #pragma unroll
        for (int ns = 0; ns < 8; ns++)
            #pragma unroll
            for (int q = 0; q < 4; q++) acc[ms][ns][q] = 0.0f;

    int tig = lane & 3, gid = lane >> 2;
    float rs[2][2] = {{0.f, 0.f}, {0.f, 0.f}};

    // ---- flat mainloop over 64 (cb, k) chunks ----
    #pragma unroll 1
    for (int j = 0; j < NJ; j++) {
        if (j < NJ - 1) asm volatile("cp.async.wait_group 1;");
        else            asm volatile("cp.async.wait_group 0;");
        __syncthreads();

        uint32_t ab = A0 + (j & 1) * A_STAGE;
        uint32_t bb = B0 + (j & 1) * B_STAGE;
        #pragma unroll
        for (int kk = 0; kk < 4; kk++) {
            uint32_t afr[2][4], bfr[4][4];
            #pragma unroll
            for (int ms = 0; ms < 2; ms++)
                ldsm4(ab + aOff[ms] + 16 * ((2 * kk + aDu) ^ aSw[ms]), afr[ms]);
            #pragma unroll
            for (int nj = 0; nj < 4; nj++)
                ldsm4(bb + bOff[nj] + 16 * ((2 * kk + bDu) ^ bSw[nj]), bfr[nj]);
            #pragma unroll
            for (int ms = 0; ms < 2; ms++)
                #pragma unroll
                for (int ns = 0; ns < 8; ns++)
                    mma_tf32(acc[ms][ns], afr[ms],
                             bfr[ns >> 1][(ns & 1) * 2],
                             bfr[ns >> 1][(ns & 1) * 2 + 1]);
        }
        __syncthreads();
        if (j + 2 < NJ) load_chunk(j + 2);

        if ((j & 7) == 7) {
            // ---- epilogue for finished column block (overlaps prefetch) ----
            int cb = j >> 3;
            #pragma unroll
            for (int ms = 0; ms < 2; ms++) {
                int r0 = gr0 + wm + 16 * ms + gid;
                float zs0 = g_zsq[r0];
                float zs1 = g_zsq[r0 + 8];
                #pragma unroll
                for (int ns = 0; ns < 8; ns++) {
                    int col = cb * BN + wn + 8 * ns + 2 * tig;
                    float cs0 = __ldg(&g_csq[col]);
                    float cs1 = __ldg(&g_csq[col + 1]);
                    float d00 = fmaxf(fmaf(-2.0f, acc[ms][ns][0], zs0 + cs0), 0.0f);
                    float d01 = fmaxf(fmaf(-2.0f, acc[ms][ns][1], zs0 + cs1), 0.0f);
                    float d10 = fmaxf(fmaf(-2.0f, acc[ms][ns][2], zs1 + cs0), 0.0f);
                    float d11 = fmaxf(fmaf(-2.0f, acc[ms][ns][3], zs1 + cs1), 0.0f);
                    float s00, s01, s10, s11;
                    { float x = fmaf(d00, 0.1f, 1.0f); float y = rsqrtf(x);
                      float y2 = y*y, y4 = y2*y2, y8 = y4*y4; s00 = y8*y2*y; }
                    { float x = fmaf(d01, 0.1f, 1.0f); float y = rsqrtf(x);
                      float y2 = y*y, y4 = y2*y2, y8 = y4*y4; s01 = y8*y2*y; }
                    { float x = fmaf(d10, 0.1f, 1.0f); float y = rsqrtf(x);
                      float y2 = y*y, y4 = y2*y2, y8 = y4*y4; s10 = y8*y2*y; }
                    { float x = fmaf(d11, 0.1f, 1.0f); float y = rsqrtf(x);
                      float y2 = y*y, y4 = y2*y2, y8 = y4*y4; s11 = y8*y2*y; }
                    rs[ms][0] += s00 + s01;
                    rs[ms][1] += s10 + s11;
                    *(float2*)(out + (size_t)r0 * KC + col)       = make_float2(s00, s01);
                    *(float2*)(out + (size_t)(r0 + 8) * KC + col) = make_float2(s10, s11);
                    acc[ms][ns][0] = 0.f; acc[ms][ns][1] = 0.f;
                    acc[ms][ns][2] = 0.f; acc[ms][ns][3] = 0.f;
                }
            }
        }
    }

    // ---- row-sum reduction: quad -> smem -> inv per row ----
    #pragma unroll
    for (int ms = 0; ms < 2; ms++)
        #pragma unroll
        for (int h = 0; h < 2; h++) {
            float v = rs[ms][h];
            v += __shfl_xor_sync(0xffffffffu, v, 1);
            v += __shfl_xor_sync(0xffffffffu, v, 2);
            rs[ms][h] = v;
        }
    __syncthreads();                  // tiles dead; reuse smem for reduction
    float* red = (float*)smem;        // [128 rows][2 warp_n]
    float* inv = red + 256;
    if (tig == 0) {
        #pragma unroll
        for (int ms = 0; ms < 2; ms++)
            #pragma unroll
            for (int h = 0; h < 2; h++)
                red[(wm + 16 * ms + 8 * h + gid) * 2 + wnid] = rs[ms][h];
    }
    __syncthreads();
    if (tid < BM) inv[tid] = 1.0f / (red[tid * 2] + red[tid * 2 + 1]);
    __syncthreads();

    // ---- in-CTA normalization pass over own 512KB tile (L2-hot) ----
    float4* o4 = (float4*)out + (size_t)gr0 * (KC / 4);
    #pragma unroll 4
    for (int u = 0; u < 128; u++) {
        float iv = inv[u];
        float4 v = o4[u * 256 + tid];
        v.x *= iv; v.y *= iv; v.z *= iv; v.w *= iv;
        o4[u * 256 + tid] = v;
    }
}

// ---------------------------------------------------------------------------
extern "C" void kernel_launch(void* const* d_in, const int* in_sizes, int n_in,
                              void* d_out, int out_size) {
    const float* z = (const float*)d_in[0];
    const float* c = (const float*)d_in[1];
    if (in_sizes[0] == KC * DDIM) {          // defensive: metadata order
        const float* t = z; z = c; c = t;
    }
    float* out = (float*)d_out;

    static int smem_set = 0;
    if (!smem_set) {
        cudaFuncSetAttribute(gemm_kernel,
                             cudaFuncAttributeMaxDynamicSharedMemorySize, SMEM_SZ);
        smem_set = 1;
    }

    prep_kernel<<<4224, 256>>>(z, c);
    gemm_kernel<<<NROWS / BM, 256, SMEM_SZ>>>(z, c, out);
}